// round 3
// baseline (speedup 1.0000x reference)
#include <cuda_runtime.h>
#include <math.h>

#define B_ 2
#define L_ 2048
#define D_ 2048
#define H_ 16
#define DH 128

// Scratch (allocation-free rule: static __device__ arrays)
__device__ float g_q[(size_t)B_*H_*L_*DH];   // [B,H,L,Dh]
__device__ float g_k[(size_t)B_*H_*L_*DH];   // [B,H,L,Dh]
__device__ float g_v[(size_t)B_*H_*L_*DH];   // [B,H,L,Dh]
__device__ float g_ao[(size_t)B_*L_*D_];     // [B,L,H*Dh]

// ---------------------------------------------------------------------------
// SGEMM: C[M=4096, N=2048] = A[M,K=2048] * W[K,N]
// 128x128 tile, BK=16, 256 threads, 8x8 microtile.
// mode 0: scatter output to [B,H,L,Dh] (N-tile == one head exactly)
// mode 1: plain row-major [M,N]
// ---------------------------------------------------------------------------
__global__ __launch_bounds__(256, 2)
void sgemm_kernel(const float* __restrict__ A, const float* __restrict__ W,
                  float* __restrict__ C, int mode)
{
    const int N = 2048, K = 2048;
    __shared__ float As[16][132];   // transposed A tile (padded)
    __shared__ float Bs[16][128];

    const int t  = threadIdx.x;
    const int tx = t & 15;
    const int ty = t >> 4;
    const int row0 = blockIdx.y * 128;
    const int col0 = blockIdx.x * 128;

    float acc[8][8];
#pragma unroll
    for (int i = 0; i < 8; i++)
#pragma unroll
        for (int j = 0; j < 8; j++) acc[i][j] = 0.f;

    const int am = t >> 2;          // 0..63
    const int ak = (t & 3) << 2;    // 0,4,8,12
    const int bk = t >> 5;          // 0..7
    const int bn = (t & 31) << 2;   // 0..124

    for (int kt = 0; kt < K; kt += 16) {
        float4 a0 = *(const float4*)&A[(size_t)(row0 + am)      * K + kt + ak];
        float4 a1 = *(const float4*)&A[(size_t)(row0 + am + 64) * K + kt + ak];
        float4 b0 = *(const float4*)&W[(size_t)(kt + bk)     * N + col0 + bn];
        float4 b1 = *(const float4*)&W[(size_t)(kt + bk + 8) * N + col0 + bn];
        __syncthreads();
        As[ak+0][am]    = a0.x; As[ak+1][am]    = a0.y;
        As[ak+2][am]    = a0.z; As[ak+3][am]    = a0.w;
        As[ak+0][am+64] = a1.x; As[ak+1][am+64] = a1.y;
        As[ak+2][am+64] = a1.z; As[ak+3][am+64] = a1.w;
        *(float4*)&Bs[bk][bn]     = b0;
        *(float4*)&Bs[bk + 8][bn] = b1;
        __syncthreads();
#pragma unroll
        for (int k = 0; k < 16; k++) {
            float a[8], b[8];
            *(float4*)&a[0] = *(float4*)&As[k][ty << 2];
            *(float4*)&a[4] = *(float4*)&As[k][64 + (ty << 2)];
            *(float4*)&b[0] = *(float4*)&Bs[k][tx << 2];
            *(float4*)&b[4] = *(float4*)&Bs[k][64 + (tx << 2)];
#pragma unroll
            for (int i = 0; i < 8; i++)
#pragma unroll
                for (int j = 0; j < 8; j++)
                    acc[i][j] = fmaf(a[i], b[j], acc[i][j]);
        }
    }

#pragma unroll
    for (int i = 0; i < 8; i++) {
        int mr = row0 + ((i < 4) ? ((ty << 2) + i) : (64 + (ty << 2) + i - 4));
        float4 c0 = make_float4(acc[i][0], acc[i][1], acc[i][2], acc[i][3]);
        float4 c1 = make_float4(acc[i][4], acc[i][5], acc[i][6], acc[i][7]);
        if (mode == 0) {
            int b = mr >> 11;           // / L_
            int l = mr & (L_ - 1);
            int h = col0 >> 7;          // N-tile == head
            float* dst = &C[(((size_t)(b * H_ + h)) * L_ + l) * DH];
            *(float4*)&dst[tx << 2]        = c0;
            *(float4*)&dst[64 + (tx << 2)] = c1;
        } else {
            *(float4*)&C[(size_t)mr * N + col0 + (tx << 2)]      = c0;
            *(float4*)&C[(size_t)mr * N + col0 + 64 + (tx << 2)] = c1;
        }
    }
}

// ---------------------------------------------------------------------------
// RoPE on g_q (with 1/sqrt(Dh) fold-in) and g_k. Layout [B,H,L,Dh].
// inv_freq computed in double, rounded to fp32 to match jax fp32 semantics.
// ---------------------------------------------------------------------------
__global__ void rope_kernel()
{
    int idx = blockIdx.x * blockDim.x + threadIdx.x;
    const int total = B_ * H_ * L_ * (DH / 2);
    if (idx >= total) return;
    int j  = idx & 63;
    int l  = (idx >> 6) & (L_ - 1);
    int bh = idx >> 17;                          // L_*(DH/2) = 2^17
    size_t base = ((size_t)bh * L_ + l) * DH + 2 * j;

    // inv_freq = THETA^(-2j/128) = 2^(-2j*log2(500000)/128)
    // log2(500000) = 18.931568569324174
    double invf = exp2(-(double)(2 * j) * (18.931568569324174 / 128.0));
    float ang = (float)l * (float)invf;
    float c, s;
    sincosf(ang, &s, &c);   // NOTE: sincosf(x, sin*, cos*) — sin FIRST

    const float qs = 0.08838834764831845f;  // 1/sqrt(128)
    float q0 = g_q[base], q1 = g_q[base + 1];
    g_q[base]     = (q0 * c - q1 * s) * qs;
    g_q[base + 1] = (q1 * c + q0 * s) * qs;
    float k0 = g_k[base], k1 = g_k[base + 1];
    g_k[base]     = k0 * c - k1 * s;
    g_k[base + 1] = k1 * c + k0 * s;
}

// ---------------------------------------------------------------------------
// Flash attention, causal. Br=Bc=64, 256 threads (16x16), fp32.
// Thread (ty,tx): S rows ty*4+r, S cols c*16+tx; O cols tx*4 and 64+tx*4.
// Row softmax stats reduced over the 16-lane tx group via shfl.xor.
// ---------------------------------------------------------------------------
#define KSTRIDE 132
#define PSTRIDE 68

extern __shared__ float fsm[];

__global__ __launch_bounds__(256)
void flash_kernel()
{
    float* Qs = fsm;                   // 64 x 128
    float* Ks = Qs + 64 * 128;         // 64 x 132 (padded)
    float* Vs = Ks + 64 * KSTRIDE;     // 64 x 128
    float* Ps = Vs + 64 * 128;         // 64 x 68  (padded)

    const int t  = threadIdx.x;
    const int tx = t & 15;
    const int ty = t >> 4;
    const int qt = blockIdx.x;         // q tile index
    const int bh = blockIdx.y;         // b*H + h
    const size_t hb = (size_t)bh * L_ * DH;
    const int q0 = qt * 64;

    // load Q tile
#pragma unroll
    for (int i = 0; i < 8; i++) {
        int fid = t + i * 256;
        int r = fid >> 5, c4 = (fid & 31) << 2;
        *(float4*)&Qs[r * 128 + c4] = *(const float4*)&g_q[hb + (size_t)(q0 + r) * DH + c4];
    }
    __syncthreads();

    float4 o0[4], o1[4];
    float m[4], lsum[4];
#pragma unroll
    for (int r = 0; r < 4; r++) {
        o0[r] = make_float4(0.f, 0.f, 0.f, 0.f);
        o1[r] = make_float4(0.f, 0.f, 0.f, 0.f);
        m[r] = -INFINITY;
        lsum[r] = 0.f;
    }

    for (int j0 = 0; j0 <= qt; j0++) {
        __syncthreads();   // prior PV readers of Ks/Vs done
        // load K,V tiles
#pragma unroll
        for (int i = 0; i < 8; i++) {
            int fid = t + i * 256;
            int r = fid >> 5, c4 = (fid & 31) << 2;
            size_t src = hb + (size_t)(j0 * 64 + r) * DH + c4;
            *(float4*)&Ks[r * KSTRIDE + c4] = *(const float4*)&g_k[src];
            *(float4*)&Vs[r * 128 + c4]     = *(const float4*)&g_v[src];
        }
        __syncthreads();

        // S = Q K^T  (4x4 per thread)
        float s[4][4];
#pragma unroll
        for (int r = 0; r < 4; r++)
#pragma unroll
            for (int c = 0; c < 4; c++) s[r][c] = 0.f;

#pragma unroll 4
        for (int d4 = 0; d4 < 32; d4++) {
            float4 kf[4];
#pragma unroll
            for (int c = 0; c < 4; c++)
                kf[c] = *(float4*)&Ks[(c * 16 + tx) * KSTRIDE + (d4 << 2)];
#pragma unroll
            for (int r = 0; r < 4; r++) {
                float4 qf = *(float4*)&Qs[((ty << 2) + r) * 128 + (d4 << 2)];
#pragma unroll
                for (int c = 0; c < 4; c++) {
                    s[r][c] = fmaf(qf.x, kf[c].x, s[r][c]);
                    s[r][c] = fmaf(qf.y, kf[c].y, s[r][c]);
                    s[r][c] = fmaf(qf.z, kf[c].z, s[r][c]);
                    s[r][c] = fmaf(qf.w, kf[c].w, s[r][c]);
                }
            }
        }

        // causal mask (only on the diagonal tile)
        if (j0 == qt) {
#pragma unroll
            for (int r = 0; r < 4; r++) {
                int qr = q0 + (ty << 2) + r;
#pragma unroll
                for (int c = 0; c < 4; c++) {
                    int kc = j0 * 64 + c * 16 + tx;
                    if (kc > qr) s[r][c] = -INFINITY;
                }
            }
        }

        // online softmax update + write P to smem
#pragma unroll
        for (int r = 0; r < 4; r++) {
            float mt = fmaxf(fmaxf(s[r][0], s[r][1]), fmaxf(s[r][2], s[r][3]));
#pragma unroll
            for (int o = 8; o; o >>= 1)
                mt = fmaxf(mt, __shfl_xor_sync(0xffffffffu, mt, o));
            float mn = fmaxf(m[r], mt);
            float alpha = expf(m[r] - mn);
            m[r] = mn;
            float rs = 0.f;
#pragma unroll
            for (int c = 0; c < 4; c++) {
                float p = expf(s[r][c] - mn);
                rs += p;
                Ps[((ty << 2) + r) * PSTRIDE + c * 16 + tx] = p;
            }
#pragma unroll
            for (int o = 8; o; o >>= 1)
                rs += __shfl_xor_sync(0xffffffffu, rs, o);
            lsum[r] = lsum[r] * alpha + rs;
            o0[r].x *= alpha; o0[r].y *= alpha; o0[r].z *= alpha; o0[r].w *= alpha;
            o1[r].x *= alpha; o1[r].y *= alpha; o1[r].z *= alpha; o1[r].w *= alpha;
        }
        __syncthreads();   // P ready

        // O += P V
#pragma unroll 2
        for (int c4 = 0; c4 < 16; c4++) {
            float4 pv[4];
#pragma unroll
            for (int r = 0; r < 4; r++)
                pv[r] = *(float4*)&Ps[((ty << 2) + r) * PSTRIDE + (c4 << 2)];
#pragma unroll
            for (int qq = 0; qq < 4; qq++) {
                int cc = (c4 << 2) + qq;
                float4 v0 = *(float4*)&Vs[cc * 128 + (tx << 2)];
                float4 v1 = *(float4*)&Vs[cc * 128 + 64 + (tx << 2)];
#pragma unroll
                for (int r = 0; r < 4; r++) {
                    float p = (qq == 0) ? pv[r].x : (qq == 1) ? pv[r].y
                            : (qq == 2) ? pv[r].z : pv[r].w;
                    o0[r].x = fmaf(p, v0.x, o0[r].x);
                    o0[r].y = fmaf(p, v0.y, o0[r].y);
                    o0[r].z = fmaf(p, v0.z, o0[r].z);
                    o0[r].w = fmaf(p, v0.w, o0[r].w);
                    o1[r].x = fmaf(p, v1.x, o1[r].x);
                    o1[r].y = fmaf(p, v1.y, o1[r].y);
                    o1[r].z = fmaf(p, v1.z, o1[r].z);
                    o1[r].w = fmaf(p, v1.w, o1[r].w);
                }
            }
        }
    }

    // epilogue: normalize, write [B, L, H*Dh]
    const int b = bh >> 4, h = bh & 15;
#pragma unroll
    for (int r = 0; r < 4; r++) {
        float inv = 1.f / lsum[r];
        int qr = q0 + (ty << 2) + r;
        float* dst = &g_ao[(((size_t)b * L_ + qr) * H_ + h) * DH];
        float4 w0 = make_float4(o0[r].x * inv, o0[r].y * inv, o0[r].z * inv, o0[r].w * inv);
        float4 w1 = make_float4(o1[r].x * inv, o1[r].y * inv, o1[r].z * inv, o1[r].w * inv);
        *(float4*)&dst[tx << 2]        = w0;
        *(float4*)&dst[64 + (tx << 2)] = w1;
    }
}

// ---------------------------------------------------------------------------
static const size_t FSMEM =
    (size_t)(64 * 128 + 64 * KSTRIDE + 64 * 128 + 64 * PSTRIDE) * sizeof(float);

extern "C" void kernel_launch(void* const* d_in, const int* in_sizes, int n_in,
                              void* d_out, int out_size)
{
    const float* x  = (const float*)d_in[0];
    const float* Wq = (const float*)d_in[1];
    const float* Wk = (const float*)d_in[2];
    const float* Wv = (const float*)d_in[3];
    const float* Wo = (const float*)d_in[4];
    float* out = (float*)d_out;

    float *qp, *kp, *vp, *aop;
    cudaGetSymbolAddress((void**)&qp,  g_q);
    cudaGetSymbolAddress((void**)&kp,  g_k);
    cudaGetSymbolAddress((void**)&vp,  g_v);
    cudaGetSymbolAddress((void**)&aop, g_ao);

    cudaFuncSetAttribute(flash_kernel,
                         cudaFuncAttributeMaxDynamicSharedMemorySize, (int)FSMEM);

    dim3 ggrid(16, 32);   // N/128 x M/128
    sgemm_kernel<<<ggrid, 256>>>(x, Wq, qp, 0);
    sgemm_kernel<<<ggrid, 256>>>(x, Wk, kp, 0);
    sgemm_kernel<<<ggrid, 256>>>(x, Wv, vp, 0);

    rope_kernel<<<(B_ * H_ * L_ * (DH / 2)) / 256, 256>>>();

    flash_kernel<<<dim3(32, 32), 256, FSMEM>>>();

    sgemm_kernel<<<ggrid, 256>>>(aop, Wo, out, 1);
}

// round 6
// speedup vs baseline: 1.9282x; 1.9282x over previous
#include <cuda_runtime.h>
#include <cuda_bf16.h>
#include <math.h>
#include <stdint.h>

#define B_ 2
#define L_ 2048
#define D_ 2048
#define H_ 16
#define DH 128
#define M_ 4096           // B*L
#define KTOT 2048

// ---------------- scratch (__device__ globals; no allocation) ----------------
__device__ float g_q[(size_t)B_*H_*L_*DH];
__device__ float g_k[(size_t)B_*H_*L_*DH];
__device__ float g_v[(size_t)B_*H_*L_*DH];
__device__ float g_ao[(size_t)B_*L_*D_];
__device__ __nv_bfloat16 g_xhi[(size_t)M_*KTOT];
__device__ __nv_bfloat16 g_xlo[(size_t)M_*KTOT];
__device__ __nv_bfloat16 g_whi[(size_t)D_*KTOT];   // transposed weights [N,K]
__device__ __nv_bfloat16 g_wlo[(size_t)D_*KTOT];

// ---------------- helpers (baseline PTX only: sm_80-class features) ----------
__device__ __forceinline__ uint32_t smem_u32(const void* p) {
    uint32_t a;
    asm("{ .reg .u64 t; cvta.to.shared.u64 t, %1; cvt.u32.u64 %0, t; }" : "=r"(a) : "l"(p));
    return a;
}
#define SWZ128(off) ((off) ^ (((off) >> 3) & 0x70))

#define CPASYNC16(sa, ga) \
    asm volatile("cp.async.cg.shared.global [%0], [%1], 16;" :: "r"(sa), "l"(ga) : "memory")
#define CPCOMMIT() asm volatile("cp.async.commit_group;" ::: "memory")
#define CPWAIT(n)  asm volatile("cp.async.wait_group %0;" :: "n"(n) : "memory")

#define LDSM4(R, addr)                                                        \
    asm volatile("ldmatrix.sync.aligned.m8n8.x4.shared.b16 {%0,%1,%2,%3}, [%4];" \
        : "=r"((R)[0]), "=r"((R)[1]), "=r"((R)[2]), "=r"((R)[3]) : "r"(addr))

#define MMA16816(d, a, b0, b1)                                                \
    asm volatile("mma.sync.aligned.m16n8k16.row.col.f32.bf16.bf16.f32 "       \
        "{%0,%1,%2,%3}, {%4,%5,%6,%7}, {%8,%9}, {%0,%1,%2,%3};"               \
        : "+f"((d)[0]), "+f"((d)[1]), "+f"((d)[2]), "+f"((d)[3])              \
        : "r"((a)[0]), "r"((a)[1]), "r"((a)[2]), "r"((a)[3]), "r"(b0), "r"(b1))

// ---------------------------------------------------------------------------
// fp32 -> bf16 hi/lo split, same layout
// ---------------------------------------------------------------------------
__global__ void conv_plain(const float* __restrict__ in,
                           __nv_bfloat16* __restrict__ hi,
                           __nv_bfloat16* __restrict__ lo, int n4)
{
    int i = blockIdx.x * blockDim.x + threadIdx.x;
    if (i >= n4) return;
    float4 v = ((const float4*)in)[i];
    __nv_bfloat16 h0 = __float2bfloat16(v.x);
    __nv_bfloat16 h1 = __float2bfloat16(v.y);
    __nv_bfloat16 h2 = __float2bfloat16(v.z);
    __nv_bfloat16 h3 = __float2bfloat16(v.w);
    __nv_bfloat16 l0 = __float2bfloat16(v.x - __bfloat162float(h0));
    __nv_bfloat16 l1 = __float2bfloat16(v.y - __bfloat162float(h1));
    __nv_bfloat16 l2 = __float2bfloat16(v.z - __bfloat162float(h2));
    __nv_bfloat16 l3 = __float2bfloat16(v.w - __bfloat162float(h3));
    __nv_bfloat162* hp = (__nv_bfloat162*)hi;
    __nv_bfloat162* lp = (__nv_bfloat162*)lo;
    hp[2*i]   = __nv_bfloat162{h0, h1};
    hp[2*i+1] = __nv_bfloat162{h2, h3};
    lp[2*i]   = __nv_bfloat162{l0, l1};
    lp[2*i+1] = __nv_bfloat162{l2, l3};
}

// ---------------------------------------------------------------------------
// W [K,N] fp32 -> Wt [N,K] bf16 hi/lo (32x32 smem tile transpose)
// ---------------------------------------------------------------------------
__global__ void conv_T(const float* __restrict__ W,
                       __nv_bfloat16* __restrict__ hi,
                       __nv_bfloat16* __restrict__ lo)
{
    __shared__ float tl[32][33];
    const int n0 = blockIdx.x * 32, k0 = blockIdx.y * 32;
    const int tx = threadIdx.x, ty = threadIdx.y;   // 32 x 8
#pragma unroll
    for (int i = 0; i < 4; i++)
        tl[ty + 8*i][tx] = W[(size_t)(k0 + ty + 8*i) * D_ + n0 + tx];
    __syncthreads();
#pragma unroll
    for (int i = 0; i < 4; i++) {
        float v = tl[tx][ty + 8*i];
        __nv_bfloat16 h = __float2bfloat16(v);
        __nv_bfloat16 l = __float2bfloat16(v - __bfloat162float(h));
        size_t o = (size_t)(n0 + ty + 8*i) * KTOT + k0 + tx;
        hi[o] = h;
        lo[o] = l;
    }
}

// ---------------------------------------------------------------------------
// HMMA bf16 split GEMM: C[M,N] = A[M,K] * Wt[N,K]^T  (3-term hi/lo)
// 128x128 tile, BK=64, 8 warps (2x4), warp tile 64x32, mma.m16n8k16,
// cp.async 2-stage pipeline, SW128-swizzled smem.
// mode 0: scatter to [B,H,L,Dh]; mode 1: row-major [M,N]
// ---------------------------------------------------------------------------
#define GTM 128
#define GTN 128
#define KC  64
#define NCH (KTOT / KC)
#define STAGEB 65536           // Ahi|Alo|Bhi|Blo, 16KB each
#define GSMEM (2 * STAGEB)

extern __shared__ char gsm[];

__global__ __launch_bounds__(256, 1)
void gemm_bf16(const __nv_bfloat16* __restrict__ Ahi, const __nv_bfloat16* __restrict__ Alo,
               const __nv_bfloat16* __restrict__ Bhi, const __nv_bfloat16* __restrict__ Blo,
               float* __restrict__ C, int mode)
{
    const uint32_t sb = smem_u32(gsm);
    const int t = threadIdx.x;
    const int lane = t & 31, wid = t >> 5;
    const int wm = wid & 1, wn = wid >> 1;        // 2 x 4 warp grid
    const int row0 = blockIdx.y * GTM;
    const int col0 = blockIdx.x * GTN;

    float acc[4][4][4];
#pragma unroll
    for (int i = 0; i < 4; i++)
#pragma unroll
        for (int j = 0; j < 4; j++)
#pragma unroll
            for (int q = 0; q < 4; q++) acc[i][j][q] = 0.f;

#define LOAD_STAGE(ch, s) do {                                                \
    _Pragma("unroll")                                                         \
    for (int i = 0; i < 4; i++) {                                             \
        int u = t + i * 256;                                                  \
        int rr = u >> 3;                                                      \
        int ce = (u & 7) << 3;         /* col in bf16 elems: 0,8,...,56 */    \
        uint32_t sw = sb + (s) * STAGEB + SWZ128((rr << 7) + (ce << 1));      \
        size_t goA = (size_t)(row0 + rr) * KTOT + (ch) * KC + ce;             \
        size_t goB = (size_t)(col0 + rr) * KTOT + (ch) * KC + ce;             \
        CPASYNC16(sw,         Ahi + goA);                                     \
        CPASYNC16(sw + 16384, Alo + goA);                                     \
        CPASYNC16(sw + 32768, Bhi + goB);                                     \
        CPASYNC16(sw + 49152, Blo + goB);                                     \
    }                                                                         \
    CPCOMMIT();                                                               \
} while (0)

    LOAD_STAGE(0, 0);

    for (int ch = 0; ch < NCH; ch++) {
        if (ch + 1 < NCH) {
            LOAD_STAGE(ch + 1, (ch + 1) & 1);
            CPWAIT(1);
        } else {
            CPWAIT(0);
        }
        __syncthreads();

        const uint32_t base = sb + (ch & 1) * STAGEB;
#pragma unroll
        for (int k16 = 0; k16 < 4; k16++) {
            const int kb = k16 * 32;   // byte offset of this k16 step
            uint32_t ah[4][4], al[4][4], bh2[2][4], bl2[2][4];
#pragma unroll
            for (int mf = 0; mf < 4; mf++) {
                int m = wm * 64 + mf * 16 + ((lane >> 3) & 1) * 8 + (lane & 7);
                uint32_t ad = base + SWZ128((m << 7) + kb + ((lane >> 4) << 4));
                LDSM4(ah[mf], ad);
                LDSM4(al[mf], ad + 16384);
            }
#pragma unroll
            for (int nf2 = 0; nf2 < 2; nf2++) {
                int n = wn * 32 + nf2 * 16 + ((lane >> 4) & 1) * 8 + (lane & 7);
                uint32_t bd = base + 32768 + SWZ128((n << 7) + kb + (((lane >> 3) & 1) << 4));
                LDSM4(bh2[nf2], bd);
                LDSM4(bl2[nf2], bd + 16384);
            }
            // term-major issue: 16 independent mmas between accumulator reuses
#pragma unroll
            for (int mf = 0; mf < 4; mf++)
#pragma unroll
                for (int nf = 0; nf < 4; nf++)
                    MMA16816(acc[mf][nf], ah[mf], bh2[nf >> 1][(nf & 1) * 2],
                             bh2[nf >> 1][(nf & 1) * 2 + 1]);
#pragma unroll
            for (int mf = 0; mf < 4; mf++)
#pragma unroll
                for (int nf = 0; nf < 4; nf++)
                    MMA16816(acc[mf][nf], ah[mf], bl2[nf >> 1][(nf & 1) * 2],
                             bl2[nf >> 1][(nf & 1) * 2 + 1]);
#pragma unroll
            for (int mf = 0; mf < 4; mf++)
#pragma unroll
                for (int nf = 0; nf < 4; nf++)
                    MMA16816(acc[mf][nf], al[mf], bh2[nf >> 1][(nf & 1) * 2],
                             bh2[nf >> 1][(nf & 1) * 2 + 1]);
        }
        __syncthreads();
    }

    // epilogue
#pragma unroll
    for (int mf = 0; mf < 4; mf++) {
        int mrow = row0 + wm * 64 + mf * 16 + (lane >> 2);
        float *d0, *d1;
        if (mode == 0) {
            int b = mrow >> 11, l = mrow & (L_ - 1), h = col0 >> 7;
            d0 = &C[(((size_t)(b * H_ + h)) * L_ + l) * DH];
            d1 = d0 + 8 * DH;
        } else {
            d0 = &C[(size_t)mrow * D_ + col0];
            d1 = d0 + (size_t)8 * D_;
        }
#pragma unroll
        for (int nf = 0; nf < 4; nf++) {
            int n = wn * 32 + nf * 8 + (lane & 3) * 2;
            *(float2*)&d0[n] = make_float2(acc[mf][nf][0], acc[mf][nf][1]);
            *(float2*)&d1[n] = make_float2(acc[mf][nf][2], acc[mf][nf][3]);
        }
    }
}

// ---------------------------------------------------------------------------
// RoPE (q with 1/sqrt(Dh) fold-in) + k. [B,H,L,Dh]; smem inv_freq table.
// ---------------------------------------------------------------------------
__global__ void rope_kernel()
{
    __shared__ float invf_s[64];
    const int tid = threadIdx.x;
    if (tid < 64)
        invf_s[tid] = (float)exp2(-(double)(2 * tid) * (18.931568569324174 / 128.0));
    __syncthreads();

    int idx = blockIdx.x * 256 + tid;
    if (idx >= B_ * H_ * L_ * (DH / 2)) return;
    int j  = idx & 63;
    int l  = (idx >> 6) & (L_ - 1);
    int bh = idx >> 17;
    size_t base = ((size_t)bh * L_ + l) * DH + 2 * j;

    float ang = (float)l * invf_s[j];
    float c, s;
    sincosf(ang, &s, &c);

    const float qs = 0.08838834764831845f;
    float q0 = g_q[base], q1 = g_q[base + 1];
    g_q[base]     = (q0 * c - q1 * s) * qs;
    g_q[base + 1] = (q1 * c + q0 * s) * qs;
    float k0 = g_k[base], k1 = g_k[base + 1];
    g_k[base]     = k0 * c - k1 * s;
    g_k[base + 1] = k1 * c + k0 * s;
}

// ---------------------------------------------------------------------------
// Flash attention, causal. Br=Bc=64, 256 threads, fp32 (unchanged).
// ---------------------------------------------------------------------------
#define KSTRIDE 132
#define PSTRIDE 68

extern __shared__ float fsm[];

__global__ __launch_bounds__(256)
void flash_kernel()
{
    float* Qs = fsm;
    float* Ks = Qs + 64 * 128;
    float* Vs = Ks + 64 * KSTRIDE;
    float* Ps = Vs + 64 * 128;

    const int t  = threadIdx.x;
    const int tx = t & 15;
    const int ty = t >> 4;
    const int qt = blockIdx.x;
    const int bh = blockIdx.y;
    const size_t hb = (size_t)bh * L_ * DH;
    const int q0 = qt * 64;

#pragma unroll
    for (int i = 0; i < 8; i++) {
        int fid = t + i * 256;
        int r = fid >> 5, c4 = (fid & 31) << 2;
        *(float4*)&Qs[r * 128 + c4] = *(const float4*)&g_q[hb + (size_t)(q0 + r) * DH + c4];
    }
    __syncthreads();

    float4 o0[4], o1[4];
    float m[4], lsum[4];
#pragma unroll
    for (int r = 0; r < 4; r++) {
        o0[r] = make_float4(0.f, 0.f, 0.f, 0.f);
        o1[r] = make_float4(0.f, 0.f, 0.f, 0.f);
        m[r] = -INFINITY;
        lsum[r] = 0.f;
    }

    for (int j0 = 0; j0 <= qt; j0++) {
        __syncthreads();
#pragma unroll
        for (int i = 0; i < 8; i++) {
            int fid = t + i * 256;
            int r = fid >> 5, c4 = (fid & 31) << 2;
            size_t src = hb + (size_t)(j0 * 64 + r) * DH + c4;
            *(float4*)&Ks[r * KSTRIDE + c4] = *(const float4*)&g_k[src];
            *(float4*)&Vs[r * 128 + c4]     = *(const float4*)&g_v[src];
        }
        __syncthreads();

        float s[4][4];
#pragma unroll
        for (int r = 0; r < 4; r++)
#pragma unroll
            for (int c = 0; c < 4; c++) s[r][c] = 0.f;

#pragma unroll 4
        for (int d4 = 0; d4 < 32; d4++) {
            float4 kf[4];
#pragma unroll
            for (int c = 0; c < 4; c++)
                kf[c] = *(float4*)&Ks[(c * 16 + tx) * KSTRIDE + (d4 << 2)];
#pragma unroll
            for (int r = 0; r < 4; r++) {
                float4 qf = *(float4*)&Qs[((ty << 2) + r) * 128 + (d4 << 2)];
#pragma unroll
                for (int c = 0; c < 4; c++) {
                    s[r][c] = fmaf(qf.x, kf[c].x, s[r][c]);
                    s[r][c] = fmaf(qf.y, kf[c].y, s[r][c]);
                    s[r][c] = fmaf(qf.z, kf[c].z, s[r][c]);
                    s[r][c] = fmaf(qf.w, kf[c].w, s[r][c]);
                }
            }
        }

        if (j0 == qt) {
#pragma unroll
            for (int r = 0; r < 4; r++) {
                int qr = q0 + (ty << 2) + r;
#pragma unroll
                for (int c = 0; c < 4; c++) {
                    int kc = j0 * 64 + c * 16 + tx;
                    if (kc > qr) s[r][c] = -INFINITY;
                }
            }
        }

#pragma unroll
        for (int r = 0; r < 4; r++) {
            float mt = fmaxf(fmaxf(s[r][0], s[r][1]), fmaxf(s[r][2], s[r][3]));
#pragma unroll
            for (int o = 8; o; o >>= 1)
                mt = fmaxf(mt, __shfl_xor_sync(0xffffffffu, mt, o));
            float mn = fmaxf(m[r], mt);
            float alpha = expf(m[r] - mn);
            m[r] = mn;
            float rs = 0.f;
#pragma unroll
            for (int c = 0; c < 4; c++) {
                float p = expf(s[r][c] - mn);
                rs += p;
                Ps[((ty << 2) + r) * PSTRIDE + c * 16 + tx] = p;
            }
#pragma unroll
            for (int o = 8; o; o >>= 1)
                rs += __shfl_xor_sync(0xffffffffu, rs, o);
            lsum[r] = lsum[r] * alpha + rs;
            o0[r].x *= alpha; o0[r].y *= alpha; o0[r].z *= alpha; o0[r].w *= alpha;
            o1[r].x *= alpha; o1[r].y *= alpha; o1[r].z *= alpha; o1[r].w *= alpha;
        }
        __syncthreads();

#pragma unroll 2
        for (int c4 = 0; c4 < 16; c4++) {
            float4 pv[4];
#pragma unroll
            for (int r = 0; r < 4; r++)
                pv[r] = *(float4*)&Ps[((ty << 2) + r) * PSTRIDE + (c4 << 2)];
#pragma unroll
            for (int qq = 0; qq < 4; qq++) {
                int cc = (c4 << 2) + qq;
                float4 v0 = *(float4*)&Vs[cc * 128 + (tx << 2)];
                float4 v1 = *(float4*)&Vs[cc * 128 + 64 + (tx << 2)];
#pragma unroll
                for (int r = 0; r < 4; r++) {
                    float p = (qq == 0) ? pv[r].x : (qq == 1) ? pv[r].y
                            : (qq == 2) ? pv[r].z : pv[r].w;
                    o0[r].x = fmaf(p, v0.x, o0[r].x);
                    o0[r].y = fmaf(p, v0.y, o0[r].y);
                    o0[r].z = fmaf(p, v0.z, o0[r].z);
                    o0[r].w = fmaf(p, v0.w, o0[r].w);
                    o1[r].x = fmaf(p, v1.x, o1[r].x);
                    o1[r].y = fmaf(p, v1.y, o1[r].y);
                    o1[r].z = fmaf(p, v1.z, o1[r].z);
                    o1[r].w = fmaf(p, v1.w, o1[r].w);
                }
            }
        }
    }

    const int b = bh >> 4, h = bh & 15;
#pragma unroll
    for (int r = 0; r < 4; r++) {
        float inv = 1.f / lsum[r];
        int qr = q0 + (ty << 2) + r;
        float* dst = &g_ao[(((size_t)b * L_ + qr) * H_ + h) * DH];
        float4 w0 = make_float4(o0[r].x * inv, o0[r].y * inv, o0[r].z * inv, o0[r].w * inv);
        float4 w1 = make_float4(o1[r].x * inv, o1[r].y * inv, o1[r].z * inv, o1[r].w * inv);
        *(float4*)&dst[tx << 2]        = w0;
        *(float4*)&dst[64 + (tx << 2)] = w1;
    }
}

// ---------------------------------------------------------------------------
static const size_t FSMEM =
    (size_t)(64 * 128 + 64 * KSTRIDE + 64 * 128 + 64 * PSTRIDE) * sizeof(float);

extern "C" void kernel_launch(void* const* d_in, const int* in_sizes, int n_in,
                              void* d_out, int out_size)
{
    const float* x  = (const float*)d_in[0];
    const float* Wq = (const float*)d_in[1];
    const float* Wk = (const float*)d_in[2];
    const float* Wv = (const float*)d_in[3];
    const float* Wo = (const float*)d_in[4];
    float* out = (float*)d_out;

    float *qp, *kp, *vp, *aop;
    __nv_bfloat16 *xh, *xl, *wh, *wl;
    cudaGetSymbolAddress((void**)&qp,  g_q);
    cudaGetSymbolAddress((void**)&kp,  g_k);
    cudaGetSymbolAddress((void**)&vp,  g_v);
    cudaGetSymbolAddress((void**)&aop, g_ao);
    cudaGetSymbolAddress((void**)&xh,  g_xhi);
    cudaGetSymbolAddress((void**)&xl,  g_xlo);
    cudaGetSymbolAddress((void**)&wh,  g_whi);
    cudaGetSymbolAddress((void**)&wl,  g_wlo);

    cudaFuncSetAttribute(flash_kernel,
                         cudaFuncAttributeMaxDynamicSharedMemorySize, (int)FSMEM);
    cudaFuncSetAttribute(gemm_bf16,
                         cudaFuncAttributeMaxDynamicSharedMemorySize, GSMEM);

    const int n4 = M_ * KTOT / 4;
    dim3 tgrid(D_ / 32, KTOT / 32), tblk(32, 8);
    dim3 ggrid(D_ / GTN, M_ / GTM);   // (16, 32)

    conv_plain<<<(n4 + 255) / 256, 256>>>(x, xh, xl, n4);

    conv_T<<<tgrid, tblk>>>(Wq, wh, wl);
    gemm_bf16<<<ggrid, 256, GSMEM>>>(xh, xl, wh, wl, qp, 0);
    conv_T<<<tgrid, tblk>>>(Wk, wh, wl);
    gemm_bf16<<<ggrid, 256, GSMEM>>>(xh, xl, wh, wl, kp, 0);
    conv_T<<<tgrid, tblk>>>(Wv, wh, wl);
    gemm_bf16<<<ggrid, 256, GSMEM>>>(xh, xl, wh, wl, vp, 0);

    rope_kernel<<<(B_ * H_ * L_ * (DH / 2)) / 256, 256>>>();

    flash_kernel<<<dim3(32, 32), 256, FSMEM>>>();

    conv_plain<<<(n4 + 255) / 256, 256>>>(aop, xh, xl, n4);
    conv_T<<<tgrid, tblk>>>(Wo, wh, wl);
    gemm_bf16<<<ggrid, 256, GSMEM>>>(xh, xl, wh, wl, out, 1);
}

// round 9
// speedup vs baseline: 2.9368x; 1.5231x over previous
#include <cuda_runtime.h>
#include <cuda_bf16.h>
#include <math.h>
#include <stdint.h>

#define B_ 2
#define L_ 2048
#define D_ 2048
#define H_ 16
#define DH 128
#define M_ 4096           // B*L
#define KTOT 2048

// ---------------- scratch (__device__ globals; no allocation) ----------------
__device__ float g_q[(size_t)B_*H_*L_*DH];            // fp32 q (pre-rope)
__device__ float g_k[(size_t)B_*H_*L_*DH];            // fp32 k (pre-rope)
__device__ float g_ao[(size_t)B_*L_*D_];              // attention out [B,L,H*Dh]
__device__ __nv_bfloat16 g_qh[(size_t)B_*H_*L_*DH];   // post-rope hi/lo
__device__ __nv_bfloat16 g_ql[(size_t)B_*H_*L_*DH];
__device__ __nv_bfloat16 g_kh[(size_t)B_*H_*L_*DH];
__device__ __nv_bfloat16 g_kl[(size_t)B_*H_*L_*DH];
__device__ __nv_bfloat16 g_vh[(size_t)B_*H_*L_*DH];
__device__ __nv_bfloat16 g_vl[(size_t)B_*H_*L_*DH];
__device__ __nv_bfloat16 g_xhi[(size_t)M_*KTOT];
__device__ __nv_bfloat16 g_xlo[(size_t)M_*KTOT];
__device__ __nv_bfloat16 g_whi[(size_t)D_*KTOT];      // transposed weights [N,K]
__device__ __nv_bfloat16 g_wlo[(size_t)D_*KTOT];

// ---------------- helpers (baseline PTX only) ----------
__device__ __forceinline__ uint32_t smem_u32(const void* p) {
    uint32_t a;
    asm("{ .reg .u64 t; cvta.to.shared.u64 t, %1; cvt.u32.u64 %0, t; }" : "=r"(a) : "l"(p));
    return a;
}
#define SWZ128(off) ((off) ^ (((off) >> 3) & 0x70))

#define CPASYNC16(sa, ga) \
    asm volatile("cp.async.cg.shared.global [%0], [%1], 16;" :: "r"(sa), "l"(ga) : "memory")
#define CPCOMMIT() asm volatile("cp.async.commit_group;" ::: "memory")
#define CPWAIT(n)  asm volatile("cp.async.wait_group %0;" :: "n"(n) : "memory")

#define LDSM4(R, addr)                                                        \
    asm volatile("ldmatrix.sync.aligned.m8n8.x4.shared.b16 {%0,%1,%2,%3}, [%4];" \
        : "=r"((R)[0]), "=r"((R)[1]), "=r"((R)[2]), "=r"((R)[3]) : "r"(addr))
#define LDSM4T(R, addr)                                                       \
    asm volatile("ldmatrix.sync.aligned.m8n8.x4.trans.shared.b16 {%0,%1,%2,%3}, [%4];" \
        : "=r"((R)[0]), "=r"((R)[1]), "=r"((R)[2]), "=r"((R)[3]) : "r"(addr))

#define MMA16816(d, a, b0, b1)                                                \
    asm volatile("mma.sync.aligned.m16n8k16.row.col.f32.bf16.bf16.f32 "       \
        "{%0,%1,%2,%3}, {%4,%5,%6,%7}, {%8,%9}, {%0,%1,%2,%3};"               \
        : "+f"((d)[0]), "+f"((d)[1]), "+f"((d)[2]), "+f"((d)[3])              \
        : "r"((a)[0]), "r"((a)[1]), "r"((a)[2]), "r"((a)[3]), "r"(b0), "r"(b1))

// ---------------------------------------------------------------------------
// fp32 -> bf16 hi/lo split, same layout
// ---------------------------------------------------------------------------
__global__ void conv_plain(const float* __restrict__ in,
                           __nv_bfloat16* __restrict__ hi,
                           __nv_bfloat16* __restrict__ lo, int n4)
{
    int i = blockIdx.x * blockDim.x + threadIdx.x;
    if (i >= n4) return;
    float4 v = ((const float4*)in)[i];
    __nv_bfloat16 h0 = __float2bfloat16(v.x);
    __nv_bfloat16 h1 = __float2bfloat16(v.y);
    __nv_bfloat16 h2 = __float2bfloat16(v.z);
    __nv_bfloat16 h3 = __float2bfloat16(v.w);
    __nv_bfloat16 l0 = __float2bfloat16(v.x - __bfloat162float(h0));
    __nv_bfloat16 l1 = __float2bfloat16(v.y - __bfloat162float(h1));
    __nv_bfloat16 l2 = __float2bfloat16(v.z - __bfloat162float(h2));
    __nv_bfloat16 l3 = __float2bfloat16(v.w - __bfloat162float(h3));
    __nv_bfloat162* hp = (__nv_bfloat162*)hi;
    __nv_bfloat162* lp = (__nv_bfloat162*)lo;
    hp[2*i]   = __nv_bfloat162{h0, h1};
    hp[2*i+1] = __nv_bfloat162{h2, h3};
    lp[2*i]   = __nv_bfloat162{l0, l1};
    lp[2*i+1] = __nv_bfloat162{l2, l3};
}

// ---------------------------------------------------------------------------
// W [K,N] fp32 -> Wt [N,K] bf16 hi/lo (32x32 smem tile transpose)
// ---------------------------------------------------------------------------
__global__ void conv_T(const float* __restrict__ W,
                       __nv_bfloat16* __restrict__ hi,
                       __nv_bfloat16* __restrict__ lo)
{
    __shared__ float tl[32][33];
    const int n0 = blockIdx.x * 32, k0 = blockIdx.y * 32;
    const int tx = threadIdx.x, ty = threadIdx.y;   // 32 x 8
#pragma unroll
    for (int i = 0; i < 4; i++)
        tl[ty + 8*i][tx] = W[(size_t)(k0 + ty + 8*i) * D_ + n0 + tx];
    __syncthreads();
#pragma unroll
    for (int i = 0; i < 4; i++) {
        float v = tl[tx][ty + 8*i];
        __nv_bfloat16 h = __float2bfloat16(v);
        __nv_bfloat16 l = __float2bfloat16(v - __bfloat162float(h));
        size_t o = (size_t)(n0 + ty + 8*i) * KTOT + k0 + tx;
        hi[o] = h;
        lo[o] = l;
    }
}

// ---------------------------------------------------------------------------
// HMMA bf16 split GEMM: C[M,N] = A[M,K] * Wt[N,K]^T  (3-term hi/lo)
// mode 0: fp32 scatter to [B,H,L,Dh]; mode 1: fp32 row-major [M,N];
// mode 2: bf16 hi/lo scatter to [B,H,L,Dh]
// ---------------------------------------------------------------------------
#define GTM 128
#define GTN 128
#define KC  64
#define NCH (KTOT / KC)
#define STAGEB 65536           // Ahi|Alo|Bhi|Blo, 16KB each
#define GSMEM (2 * STAGEB)

extern __shared__ char gsm[];

__global__ __launch_bounds__(256, 1)
void gemm_bf16(const __nv_bfloat16* __restrict__ Ahi, const __nv_bfloat16* __restrict__ Alo,
               const __nv_bfloat16* __restrict__ Bhi, const __nv_bfloat16* __restrict__ Blo,
               float* __restrict__ C,
               __nv_bfloat16* __restrict__ Ch, __nv_bfloat16* __restrict__ Cl,
               int mode)
{
    const uint32_t sb = smem_u32(gsm);
    const int t = threadIdx.x;
    const int lane = t & 31, wid = t >> 5;
    const int wm = wid & 1, wn = wid >> 1;        // 2 x 4 warp grid
    const int row0 = blockIdx.y * GTM;
    const int col0 = blockIdx.x * GTN;

    float acc[4][4][4];
#pragma unroll
    for (int i = 0; i < 4; i++)
#pragma unroll
        for (int j = 0; j < 4; j++)
#pragma unroll
            for (int q = 0; q < 4; q++) acc[i][j][q] = 0.f;

#define LOAD_STAGE(ch, s) do {                                                \
    _Pragma("unroll")                                                         \
    for (int i = 0; i < 4; i++) {                                             \
        int u = t + i * 256;                                                  \
        int rr = u >> 3;                                                      \
        int ce = (u & 7) << 3;                                                \
        uint32_t sw = sb + (s) * STAGEB + SWZ128((rr << 7) + (ce << 1));      \
        size_t goA = (size_t)(row0 + rr) * KTOT + (ch) * KC + ce;             \
        size_t goB = (size_t)(col0 + rr) * KTOT + (ch) * KC + ce;             \
        CPASYNC16(sw,         Ahi + goA);                                     \
        CPASYNC16(sw + 16384, Alo + goA);                                     \
        CPASYNC16(sw + 32768, Bhi + goB);                                     \
        CPASYNC16(sw + 49152, Blo + goB);                                     \
    }                                                                         \
    CPCOMMIT();                                                               \
} while (0)

    LOAD_STAGE(0, 0);

    for (int ch = 0; ch < NCH; ch++) {
        if (ch + 1 < NCH) {
            LOAD_STAGE(ch + 1, (ch + 1) & 1);
            CPWAIT(1);
        } else {
            CPWAIT(0);
        }
        __syncthreads();

        const uint32_t base = sb + (ch & 1) * STAGEB;
#pragma unroll
        for (int k16 = 0; k16 < 4; k16++) {
            const int kb = k16 * 32;
            uint32_t ah[4][4], al[4][4], bh2[2][4], bl2[2][4];
#pragma unroll
            for (int mf = 0; mf < 4; mf++) {
                int m = wm * 64 + mf * 16 + ((lane >> 3) & 1) * 8 + (lane & 7);
                uint32_t ad = base + SWZ128((m << 7) + kb + ((lane >> 4) << 4));
                LDSM4(ah[mf], ad);
                LDSM4(al[mf], ad + 16384);
            }
#pragma unroll
            for (int nf2 = 0; nf2 < 2; nf2++) {
                int n = wn * 32 + nf2 * 16 + ((lane >> 4) & 1) * 8 + (lane & 7);
                uint32_t bd = base + 32768 + SWZ128((n << 7) + kb + (((lane >> 3) & 1) << 4));
                LDSM4(bh2[nf2], bd);
                LDSM4(bl2[nf2], bd + 16384);
            }
#pragma unroll
            for (int mf = 0; mf < 4; mf++)
#pragma unroll
                for (int nf = 0; nf < 4; nf++)
                    MMA16816(acc[mf][nf], ah[mf], bh2[nf >> 1][(nf & 1) * 2],
                             bh2[nf >> 1][(nf & 1) * 2 + 1]);
#pragma unroll
            for (int mf = 0; mf < 4; mf++)
#pragma unroll
                for (int nf = 0; nf < 4; nf++)
                    MMA16816(acc[mf][nf], ah[mf], bl2[nf >> 1][(nf & 1) * 2],
                             bl2[nf >> 1][(nf & 1) * 2 + 1]);
#pragma unroll
            for (int mf = 0; mf < 4; mf++)
#pragma unroll
                for (int nf = 0; nf < 4; nf++)
                    MMA16816(acc[mf][nf], al[mf], bh2[nf >> 1][(nf & 1) * 2],
                             bh2[nf >> 1][(nf & 1) * 2 + 1]);
        }
        __syncthreads();
    }

    // epilogue
#pragma unroll
    for (int mf = 0; mf < 4; mf++) {
        int mrow = row0 + wm * 64 + mf * 16 + (lane >> 2);
        if (mode == 2) {
            int b = mrow >> 11, l = mrow & (L_ - 1), h = col0 >> 7;
            size_t base0 = (((size_t)(b * H_ + h)) * L_ + l) * DH;
            size_t base1 = base0 + (size_t)8 * DH;
#pragma unroll
            for (int nf = 0; nf < 4; nf++) {
                int n = wn * 32 + nf * 8 + (lane & 3) * 2;
#pragma unroll
                for (int half = 0; half < 2; half++) {
                    size_t bb = half ? base1 : base0;
                    float v0 = acc[mf][nf][half * 2], v1 = acc[mf][nf][half * 2 + 1];
                    __nv_bfloat16 h0 = __float2bfloat16(v0);
                    __nv_bfloat16 h1 = __float2bfloat16(v1);
                    __nv_bfloat16 e0 = __float2bfloat16(v0 - __bfloat162float(h0));
                    __nv_bfloat16 e1 = __float2bfloat16(v1 - __bfloat162float(h1));
                    *(__nv_bfloat162*)&Ch[bb + n] = __nv_bfloat162{h0, h1};
                    *(__nv_bfloat162*)&Cl[bb + n] = __nv_bfloat162{e0, e1};
                }
            }
        } else {
            float *d0, *d1;
            if (mode == 0) {
                int b = mrow >> 11, l = mrow & (L_ - 1), h = col0 >> 7;
                d0 = &C[(((size_t)(b * H_ + h)) * L_ + l) * DH];
                d1 = d0 + 8 * DH;
            } else {
                d0 = &C[(size_t)mrow * D_ + col0];
                d1 = d0 + (size_t)8 * D_;
            }
#pragma unroll
            for (int nf = 0; nf < 4; nf++) {
                int n = wn * 32 + nf * 8 + (lane & 3) * 2;
                *(float2*)&d0[n] = make_float2(acc[mf][nf][0], acc[mf][nf][1]);
                *(float2*)&d1[n] = make_float2(acc[mf][nf][2], acc[mf][nf][3]);
            }
        }
    }
}

// ---------------------------------------------------------------------------
// RoPE: read fp32 g_q/g_k, rotate (q scaled by 1/sqrt(Dh)), emit bf16 hi/lo.
// ---------------------------------------------------------------------------
__global__ void rope_kernel()
{
    __shared__ float invf_s[64];
    const int tid = threadIdx.x;
    if (tid < 64)
        invf_s[tid] = (float)exp2(-(double)(2 * tid) * (18.931568569324174 / 128.0));
    __syncthreads();

    int idx = blockIdx.x * 256 + tid;
    if (idx >= B_ * H_ * L_ * (DH / 2)) return;
    int j  = idx & 63;
    int l  = (idx >> 6) & (L_ - 1);
    int bh = idx >> 17;
    size_t base = ((size_t)bh * L_ + l) * DH + 2 * j;

    float ang = (float)l * invf_s[j];
    float c, s;
    sincosf(ang, &s, &c);   // sincosf(x, sin*, cos*) — sin FIRST

    const float qs = 0.08838834764831845f;  // 1/sqrt(128)
    float q0 = g_q[base], q1 = g_q[base + 1];
    float k0 = g_k[base], k1 = g_k[base + 1];
    float qr0 = (q0 * c - q1 * s) * qs;
    float qr1 = (q1 * c + q0 * s) * qs;
    float kr0 = k0 * c - k1 * s;
    float kr1 = k1 * c + k0 * s;

    __nv_bfloat16 qh0 = __float2bfloat16(qr0), qh1 = __float2bfloat16(qr1);
    __nv_bfloat16 kh0 = __float2bfloat16(kr0), kh1 = __float2bfloat16(kr1);
    *(__nv_bfloat162*)&g_qh[base] = __nv_bfloat162{qh0, qh1};
    *(__nv_bfloat162*)&g_ql[base] = __nv_bfloat162{
        __float2bfloat16(qr0 - __bfloat162float(qh0)),
        __float2bfloat16(qr1 - __bfloat162float(qh1))};
    *(__nv_bfloat162*)&g_kh[base] = __nv_bfloat162{kh0, kh1};
    *(__nv_bfloat162*)&g_kl[base] = __nv_bfloat162{
        __float2bfloat16(kr0 - __bfloat162float(kh0)),
        __float2bfloat16(kr1 - __bfloat162float(kh1))};
}

// ---------------------------------------------------------------------------
// HMMA flash attention, causal. Br=128, Bc=64, 8 warps (16 rows each).
// S = 3-term bf16 split; P hi/lo split; PV = Ph*Vh + Pl*Vh + Ph*Vl.
// cp.async double buffer.
// ---------------------------------------------------------------------------
#define FBR 128
#define FBC 64
#define SQH 0
#define SQL 32768
#define SKV 65536                 // stages at 65536 + s*65536
#define FSMEMB (65536 + 2 * 65536)  // 192 KB

extern __shared__ char fsm8[];

__device__ __forceinline__ uint32_t pack_bf16x2(float lo, float hi) {
    uint32_t d;
    asm("cvt.rn.bf16x2.f32 %0, %1, %2;" : "=r"(d) : "f"(hi), "f"(lo));
    return d;
}

__global__ __launch_bounds__(256, 1)
void flash_kernel()
{
    const uint32_t sb = smem_u32(fsm8);
    const int t = threadIdx.x, lane = t & 31, w = t >> 5;
    const int qt = (int)gridDim.x - 1 - (int)blockIdx.x;   // heavy tiles first
    const int bh = blockIdx.y;
    const int q0 = qt * FBR;
    const size_t hb = (size_t)bh * L_ * DH;

    // load Q hi/lo (once)
#pragma unroll
    for (int i = 0; i < 8; i++) {
        int u = t + i * 256;
        int c = u >> 10, r = (u >> 3) & 127, e8 = (u & 7) << 3;
        uint32_t so = c * 16384 + SWZ128((r << 7) + (e8 << 1));
        size_t go = hb + (size_t)(q0 + r) * DH + c * 64 + e8;
        *(uint4*)(fsm8 + SQH + so) = *(const uint4*)&g_qh[go];
        *(uint4*)(fsm8 + SQL + so) = *(const uint4*)&g_ql[go];
    }

#define LOADKV(j, s) do {                                                     \
    int kv0_ = (j) * FBC;                                                     \
    uint32_t stb = sb + SKV + (s) * 65536;                                    \
    _Pragma("unroll")                                                         \
    for (int i = 0; i < 4; i++) {                                             \
        int u = t + i * 256;                                                  \
        int c = u >> 9, r = (u >> 3) & 63, e8 = (u & 7) << 3;                 \
        uint32_t so = stb + c * 8192 + SWZ128((r << 7) + (e8 << 1));          \
        size_t go = hb + (size_t)(kv0_ + r) * DH + c * 64 + e8;               \
        CPASYNC16(so,         g_kh + go);                                     \
        CPASYNC16(so + 16384, g_kl + go);                                     \
        CPASYNC16(so + 32768, g_vh + go);                                     \
        CPASYNC16(so + 49152, g_vl + go);                                     \
    }                                                                         \
    CPCOMMIT();                                                               \
} while (0)

    const int jmax = qt * 2 + 1;
    LOADKV(0, 0);

    float o[16][4];
#pragma unroll
    for (int i = 0; i < 16; i++)
#pragma unroll
        for (int q = 0; q < 4; q++) o[i][q] = 0.f;
    float m0 = -INFINITY, m1 = -INFINITY, l0 = 0.f, l1 = 0.f;

    // per-lane invariant offsets
    const int mrow = w * 16 + ((lane >> 3) & 1) * 8 + (lane & 7);
    const int kAoff = (lane >> 4) << 4;
    const int nrow = ((lane >> 4) & 1) * 8 + (lane & 7);
    const int kBoff = ((lane >> 3) & 1) << 4;
    const int vrow = ((lane >> 3) & 1) * 8 + (lane & 7);
    const int vcol8 = ((lane >> 4) & 1) * 8;
    const int r0 = lane >> 2;          // warp-local row (also +8)
    const int cql = (lane & 3) * 2;    // col pair base within n8

    for (int j0 = 0; j0 <= jmax; j0++) {
        if (j0 < jmax) { LOADKV(j0 + 1, (j0 + 1) & 1); CPWAIT(1); }
        else CPWAIT(0);
        __syncthreads();

        const uint32_t kvb = sb + SKV + (j0 & 1) * 65536;
        const int kv0 = j0 * FBC;

        // ---- S = Q K^T (3-term) ----
        float s[8][4];
#pragma unroll
        for (int i = 0; i < 8; i++)
#pragma unroll
            for (int q = 0; q < 4; q++) s[i][q] = 0.f;

#pragma unroll
        for (int c = 0; c < 2; c++) {
#pragma unroll
            for (int kk = 0; kk < 4; kk++) {
                const int kb = kk * 32;
                uint32_t ah[4], al[4];
                uint32_t qa = sb + SQH + c * 16384 + SWZ128((mrow << 7) + kb + kAoff);
                LDSM4(ah, qa);
                LDSM4(al, qa + 32768);
#pragma unroll
                for (int ng = 0; ng < 4; ng++) {
                    uint32_t kh[4], kl[4];
                    uint32_t ka = kvb + c * 8192
                                + SWZ128(((ng * 16 + nrow) << 7) + kb + kBoff);
                    LDSM4(kh, ka);
                    LDSM4(kl, ka + 16384);
                    MMA16816(s[2*ng],   ah, kh[0], kh[1]);
                    MMA16816(s[2*ng+1], ah, kh[2], kh[3]);
                    MMA16816(s[2*ng],   ah, kl[0], kl[1]);
                    MMA16816(s[2*ng+1], ah, kl[2], kl[3]);
                    MMA16816(s[2*ng],   al, kh[0], kh[1]);
                    MMA16816(s[2*ng+1], al, kh[2], kh[3]);
                }
            }
        }

        // ---- causal mask ----
        const int qr0 = q0 + w * 16 + r0;
        if (kv0 + 63 > qr0) {
#pragma unroll
            for (int nf = 0; nf < 8; nf++) {
                int kc = kv0 + nf * 8 + cql;
                if (kc > qr0)     s[nf][0] = -INFINITY;
                if (kc + 1 > qr0) s[nf][1] = -INFINITY;
                if (kc > qr0 + 8)     s[nf][2] = -INFINITY;
                if (kc + 1 > qr0 + 8) s[nf][3] = -INFINITY;
            }
        }

        // ---- online softmax (rows warp-local; reduce over 4-lane row group) ----
        float mt0 = -INFINITY, mt1 = -INFINITY;
#pragma unroll
        for (int nf = 0; nf < 8; nf++) {
            mt0 = fmaxf(mt0, fmaxf(s[nf][0], s[nf][1]));
            mt1 = fmaxf(mt1, fmaxf(s[nf][2], s[nf][3]));
        }
        mt0 = fmaxf(mt0, __shfl_xor_sync(0xffffffffu, mt0, 1));
        mt0 = fmaxf(mt0, __shfl_xor_sync(0xffffffffu, mt0, 2));
        mt1 = fmaxf(mt1, __shfl_xor_sync(0xffffffffu, mt1, 1));
        mt1 = fmaxf(mt1, __shfl_xor_sync(0xffffffffu, mt1, 2));

        float nm0 = fmaxf(m0, mt0), nm1 = fmaxf(m1, mt1);
        float a0 = __expf(m0 - nm0), a1 = __expf(m1 - nm1);
        m0 = nm0; m1 = nm1;

        float rs0 = 0.f, rs1 = 0.f;
        uint32_t pah[4][4], pal[4][4];
#pragma unroll
        for (int kk = 0; kk < 4; kk++) {
#pragma unroll
            for (int half = 0; half < 2; half++) {
                int nf = 2 * kk + half;
                float p00 = __expf(s[nf][0] - m0);
                float p01 = __expf(s[nf][1] - m0);
                float p10 = __expf(s[nf][2] - m1);
                float p11 = __expf(s[nf][3] - m1);
                rs0 += p00 + p01;
                rs1 += p10 + p11;
                uint32_t ph0 = pack_bf16x2(p00, p01);
                uint32_t ph1 = pack_bf16x2(p10, p11);
                __nv_bfloat162 b0 = *(__nv_bfloat162*)&ph0;
                __nv_bfloat162 b1 = *(__nv_bfloat162*)&ph1;
                uint32_t pl0 = pack_bf16x2(p00 - __bfloat162float(b0.x),
                                           p01 - __bfloat162float(b0.y));
                uint32_t pl1 = pack_bf16x2(p10 - __bfloat162float(b1.x),
                                           p11 - __bfloat162float(b1.y));
                pah[kk][half * 2]     = ph0;
                pah[kk][half * 2 + 1] = ph1;
                pal[kk][half * 2]     = pl0;
                pal[kk][half * 2 + 1] = pl1;
            }
        }
        rs0 += __shfl_xor_sync(0xffffffffu, rs0, 1);
        rs0 += __shfl_xor_sync(0xffffffffu, rs0, 2);
        rs1 += __shfl_xor_sync(0xffffffffu, rs1, 1);
        rs1 += __shfl_xor_sync(0xffffffffu, rs1, 2);
        l0 = l0 * a0 + rs0;
        l1 = l1 * a1 + rs1;

#pragma unroll
        for (int nf = 0; nf < 16; nf++) {
            o[nf][0] *= a0; o[nf][1] *= a0;
            o[nf][2] *= a1; o[nf][3] *= a1;
        }

        // ---- O += Ph*(Vh+Vl) + Pl*Vh ----
#pragma unroll
        for (int kk = 0; kk < 4; kk++) {
#pragma unroll
            for (int dg = 0; dg < 8; dg++) {
                int dcol = dg * 16 + vcol8;
                int c = dcol >> 6, e = dcol & 63;
                uint32_t va = kvb + 32768 + c * 8192
                            + SWZ128(((kk * 16 + vrow) << 7) + (e << 1));
                uint32_t vh[4], vl[4];
                LDSM4T(vh, va);
                LDSM4T(vl, va + 16384);
                MMA16816(o[2*dg],   pah[kk], vh[0], vh[1]);
                MMA16816(o[2*dg+1], pah[kk], vh[2], vh[3]);
                MMA16816(o[2*dg],   pal[kk], vh[0], vh[1]);
                MMA16816(o[2*dg+1], pal[kk], vh[2], vh[3]);
                MMA16816(o[2*dg],   pah[kk], vl[0], vl[1]);
                MMA16816(o[2*dg+1], pah[kk], vl[2], vl[3]);
            }
        }
        __syncthreads();   // all warps done with this stage before it's refilled
    }

    // ---- epilogue ----
    const int b = bh >> 4, h = bh & 15;
    const float inv0 = 1.f / l0, inv1 = 1.f / l1;
    const int qrow0 = q0 + w * 16 + r0;
    float* d0 = &g_ao[((size_t)b * L_ + qrow0) * D_ + h * DH];
    float* d1 = &g_ao[((size_t)b * L_ + qrow0 + 8) * D_ + h * DH];
#pragma unroll
    for (int nf = 0; nf < 16; nf++) {
        int col = nf * 8 + cql;
        *(float2*)&d0[col] = make_float2(o[nf][0] * inv0, o[nf][1] * inv0);
        *(float2*)&d1[col] = make_float2(o[nf][2] * inv1, o[nf][3] * inv1);
    }
}

// ---------------------------------------------------------------------------
extern "C" void kernel_launch(void* const* d_in, const int* in_sizes, int n_in,
                              void* d_out, int out_size)
{
    const float* x  = (const float*)d_in[0];
    const float* Wq = (const float*)d_in[1];
    const float* Wk = (const float*)d_in[2];
    const float* Wv = (const float*)d_in[3];
    const float* Wo = (const float*)d_in[4];
    float* out = (float*)d_out;

    float *qp, *kp, *aop;
    __nv_bfloat16 *xh, *xl, *wh, *wl, *vh, *vl;
    cudaGetSymbolAddress((void**)&qp,  g_q);
    cudaGetSymbolAddress((void**)&kp,  g_k);
    cudaGetSymbolAddress((void**)&aop, g_ao);
    cudaGetSymbolAddress((void**)&xh,  g_xhi);
    cudaGetSymbolAddress((void**)&xl,  g_xlo);
    cudaGetSymbolAddress((void**)&wh,  g_whi);
    cudaGetSymbolAddress((void**)&wl,  g_wlo);
    cudaGetSymbolAddress((void**)&vh,  g_vh);
    cudaGetSymbolAddress((void**)&vl,  g_vl);

    cudaFuncSetAttribute(flash_kernel,
                         cudaFuncAttributeMaxDynamicSharedMemorySize, FSMEMB);
    cudaFuncSetAttribute(gemm_bf16,
                         cudaFuncAttributeMaxDynamicSharedMemorySize, GSMEM);

    const int n4 = M_ * KTOT / 4;
    dim3 tgrid(D_ / 32, KTOT / 32), tblk(32, 8);
    dim3 ggrid(D_ / GTN, M_ / GTM);   // (16, 32)

    conv_plain<<<(n4 + 255) / 256, 256>>>(x, xh, xl, n4);

    conv_T<<<tgrid, tblk>>>(Wq, wh, wl);
    gemm_bf16<<<ggrid, 256, GSMEM>>>(xh, xl, wh, wl, qp, nullptr, nullptr, 0);
    conv_T<<<tgrid, tblk>>>(Wk, wh, wl);
    gemm_bf16<<<ggrid, 256, GSMEM>>>(xh, xl, wh, wl, kp, nullptr, nullptr, 0);
    conv_T<<<tgrid, tblk>>>(Wv, wh, wl);
    gemm_bf16<<<ggrid, 256, GSMEM>>>(xh, xl, wh, wl, nullptr, vh, vl, 2);

    rope_kernel<<<(B_ * H_ * L_ * (DH / 2)) / 256, 256>>>();

    flash_kernel<<<dim3(16, 32), 256, FSMEMB>>>();

    conv_plain<<<(n4 + 255) / 256, 256>>>(aop, xh, xl, n4);
    conv_T<<<tgrid, tblk>>>(Wo, wh, wl);
    gemm_bf16<<<ggrid, 256, GSMEM>>>(xh, xl, wh, wl, out, nullptr, nullptr, 1);
}